// round 16
// baseline (speedup 1.0000x reference)
#include <cuda_runtime.h>
#include <cuda_bf16.h>
#include <cstdint>

#define NPATH 8192
#define LMAX 32
#define DIN 256
#define EDIM 128
#define HDIM 128
#define G4 512
#define GRP 1024
#define RTOT (NPATH*LMAX)
#define LN_EPS 1e-5f

typedef unsigned long long ull;

// ---------------- device scratch (static, no allocation) ----------------
__device__ float g_gi[(size_t)RTOT*G4]; // 512 MB
__device__ uint4 g_WinP[EDIM*16*4];     // [(n*16+kf)*4+cq] = {bh0,bh1,bl0,bl1}
__device__ uint4 g_WihP[G4*8*4];        // [(n*8+kf)*4+cq]
__device__ uint4 g_WhhP[G4*8*4];        // [(n*8+kf)*4+cq]
__device__ float g_h[NPATH*HDIM];
__device__ float g_logits[NPATH];
__device__ float g_e[NPATH];
__device__ unsigned g_gmax[GRP];
__device__ float g_gsum[GRP];
__device__ float g_cnt[GRP];
__device__ float g_wsum[GRP*HDIM];
__device__ int g_lcnt[40];
__device__ int g_lstart[40];
__device__ int g_perm[NPATH];
__device__ int g_nrows;
__device__ int g_rows[RTOT];

// ---------------- fast activations (clamped, ~1e-6 rel err) ----------------
__device__ __forceinline__ float sigm_f(float x) {
    x = fmaxf(fminf(x, 30.0f), -30.0f);
    return __fdividef(1.0f, 1.0f + __expf(-x));
}
__device__ __forceinline__ float tanh_f(float x) {
    x = fmaxf(fminf(x, 15.0f), -15.0f);
    float e = __expf(-2.0f * x);
    return __fdividef(1.0f - e, 1.0f + e);
}

__device__ __forceinline__ unsigned enc_f(float f) {
    unsigned u = __float_as_uint(f);
    return (u & 0x80000000u) ? ~u : (u | 0x80000000u);
}
__device__ __forceinline__ float dec_f(unsigned k) {
    return (k & 0x80000000u) ? __uint_as_float(k ^ 0x80000000u) : __uint_as_float(~k);
}

// ---------------- mma / ldmatrix helpers ----------------
#define MMA_BF16(Cr, a0, a1, a2, a3, b0, b1) \
    asm volatile("mma.sync.aligned.m16n8k16.row.col.f32.bf16.bf16.f32 " \
        "{%0,%1,%2,%3}, {%4,%5,%6,%7}, {%8,%9}, {%0,%1,%2,%3};" \
        : "+f"((Cr)[0]), "+f"((Cr)[1]), "+f"((Cr)[2]), "+f"((Cr)[3]) \
        : "r"(a0), "r"(a1), "r"(a2), "r"(a3), "r"(b0), "r"(b1))

#define LDSM_X4(r0, r1, r2, r3, a) \
    asm volatile("ldmatrix.sync.aligned.m8n8.x4.shared.b16 {%0,%1,%2,%3}, [%4];" \
        : "=r"(r0), "=r"(r1), "=r"(r2), "=r"(r3) : "r"(a))

__device__ __forceinline__ uint32_t smem_u32(const void* p) {
    uint32_t a;
    asm("{ .reg .u64 t; cvta.to.shared.u64 t, %1; cvt.u32.u64 %0, t; }" : "=r"(a) : "l"(p));
    return a;
}
__device__ __forceinline__ uint32_t bf2_pack(float x, float y) {
    __nv_bfloat162 v;
    v.x = __float2bfloat16(x);
    v.y = __float2bfloat16(y);
    return *(uint32_t*)&v;
}

// ---------------- sort kernels ----------------
__global__ void k_hist(const int* __restrict__ lens) {
    int n = blockIdx.x * 256 + threadIdx.x;
    if (n < NPATH) atomicAdd(&g_lcnt[lens[n]], 1);
}
__global__ void k_scan() {
    if (threadIdx.x == 0 && blockIdx.x == 0) {
        int run = 0;
        for (int l = LMAX; l >= 1; l--) { g_lstart[l] = run; run += g_lcnt[l]; }
    }
}
__global__ void k_scatter(const int* __restrict__ lens) {
    int n = blockIdx.x * 256 + threadIdx.x;
    if (n < NPATH) {
        int pos = atomicAdd(&g_lstart[lens[n]], 1);
        g_perm[pos] = n;
    }
}
__global__ void k_rowlist(const int* __restrict__ lens) {
    int n = blockIdx.x * 256 + threadIdx.x;
    if (n < NPATH) {
        int l = lens[n];
        int pos = atomicAdd(&g_nrows, l);
        int base = n * LMAX;
        for (int t = 0; t < l; t++) g_rows[pos + t] = base + t;
    }
}

// ---------------- kernel 0: fragment-pack all weights (fp32 -> bf16 hi/lo uint4) ----------------
__device__ __forceinline__ uint4 pack_frag(const float* __restrict__ W, int e) {
    float a0 = W[e], a1 = W[e + 1], a2 = W[e + 8], a3 = W[e + 9];
    __nv_bfloat16 h0 = __float2bfloat16(a0), h1 = __float2bfloat16(a1);
    __nv_bfloat16 h2 = __float2bfloat16(a2), h3 = __float2bfloat16(a3);
    uint4 v;
    v.x = bf2_pack(a0, a1);
    v.y = bf2_pack(a2, a3);
    v.z = bf2_pack(a0 - __bfloat162float(h0), a1 - __bfloat162float(h1));
    v.w = bf2_pack(a2 - __bfloat162float(h2), a3 - __bfloat162float(h3));
    return v;
}
__global__ void __launch_bounds__(256) k_prep(const float* __restrict__ W_in,
                                              const float* __restrict__ Wih,
                                              const float* __restrict__ Whh) {
    int idx = blockIdx.x * 256 + threadIdx.x;   // 40960 total
    if (idx < 8192) {
        int cq = idx & 3, kf = (idx >> 2) & 15, n = idx >> 6;
        g_WinP[idx] = pack_frag(W_in, n * DIN + kf * 16 + 2 * cq);
    } else if (idx < 24576) {
        int i2 = idx - 8192;
        int cq = i2 & 3, kf = (i2 >> 2) & 7, n = i2 >> 5;
        g_WihP[i2] = pack_frag(Wih, n * HDIM + kf * 16 + 2 * cq);
    } else if (idx < 40960) {
        int i2 = idx - 24576;
        int cq = i2 & 3, kf = (i2 >> 2) & 7, n = i2 >> 5;
        g_WhhP[i2] = pack_frag(Whh, n * HDIM + kf * 16 + 2 * cq);
    }
}

// smem offsets (b32 units) for k_fp
#define OFF_AH   0
#define OFF_AL   4608
#define OFF_XH   9216
#define OFF_XL   17920
#define OFF_RED  26624
#define OFF_GAM  27136
#define OFF_BET  27264
#define OFF_BIAS 27392
#define OFF_SROW 27904
#define FP_SMEM_B32 28032

// ---------------- kernel 1: mma-based fused projection+LN+tanh + gate GEMM ----------------
__global__ void __launch_bounds__(256, 2) k_fp(const float* __restrict__ inp,
                                               const float* __restrict__ gamma,
                                               const float* __restrict__ beta,
                                               const float* __restrict__ bih,
                                               const float* __restrict__ bhh) {
    extern __shared__ uint32_t s32[];
    __nv_bfloat16* Ah16 = (__nv_bfloat16*)(s32 + OFF_AH);
    __nv_bfloat16* Al16 = (__nv_bfloat16*)(s32 + OFF_AL);
    __nv_bfloat162* Xh2 = (__nv_bfloat162*)(s32 + OFF_XH);
    __nv_bfloat162* Xl2 = (__nv_bfloat162*)(s32 + OFF_XL);
    float2* red = (float2*)(s32 + OFF_RED);
    float* sgam = (float*)(s32 + OFF_GAM);
    float* sbet = (float*)(s32 + OFF_BET);
    float* sbias = (float*)(s32 + OFF_BIAS);
    int* srow = (int*)(s32 + OFF_SROW);

    const int tid = threadIdx.x;
    const int lane = tid & 31, wid = tid >> 5;
    const int warp_m = wid & 3, warp_n = wid >> 2;
    const int r = lane >> 2, cq = lane & 3;
    const int base = blockIdx.x * 128;
    const int nrows = g_nrows;
    if (base >= nrows) return;

    const int Lrow = ((lane >> 3) & 1) * 8 + (lane & 7);
    const int Lk8 = (lane >> 4) * 8;

    if (tid < 128) {
        srow[tid] = (base + tid < nrows) ? g_rows[base + tid] : g_rows[base];
        sgam[tid] = gamma[tid];
        sbet[tid] = beta[tid];
    }
    sbias[tid] = bih[tid] + bhh[tid];
    sbias[tid + 256] = bih[tid + 256] + bhh[tid + 256];
    __syncthreads();

    uint32_t aAh[2], aAl[2], aXh[2], aXl[2];
#pragma unroll
    for (int mt = 0; mt < 2; mt++) {
        int row = warp_m * 32 + mt * 16 + Lrow;
        aAh[mt] = smem_u32(Ah16) + (row * 72 + Lk8) * 2;
        aAl[mt] = smem_u32(Al16) + (row * 72 + Lk8) * 2;
        aXh[mt] = smem_u32(Xh2) + row * 68 * 4 + Lk8 * 2;
        aXl[mt] = smem_u32(Xl2) + row * 68 * 4 + Lk8 * 2;
    }

    // phase 1
    float C[2][8][4];
#pragma unroll
    for (int mt = 0; mt < 2; mt++)
#pragma unroll
        for (int nt = 0; nt < 8; nt++)
#pragma unroll
            for (int v = 0; v < 4; v++) C[mt][nt][v] = 0.0f;

    for (int ks = 0; ks < 4; ks++) {
        __syncthreads();
#pragma unroll
        for (int s = 0; s < 32; s++) {
            int idx = tid + s * 256;
            int row = idx >> 6, c = idx & 63;
            float v = inp[(size_t)srow[row] * DIN + ks * 64 + c];
            __nv_bfloat16 h = __float2bfloat16(v);
            Ah16[row * 72 + c] = h;
            Al16[row * 72 + c] = __float2bfloat16(v - __bfloat162float(h));
        }
        __syncthreads();
#pragma unroll
        for (int k4 = 0; k4 < 4; k4++) {
            uint32_t ah[2][4], al[2][4];
#pragma unroll
            for (int mt = 0; mt < 2; mt++) {
                LDSM_X4(ah[mt][0], ah[mt][1], ah[mt][2], ah[mt][3], aAh[mt] + k4 * 32);
                LDSM_X4(al[mt][0], al[mt][1], al[mt][2], al[mt][3], aAl[mt] + k4 * 32);
            }
            const int kf = ks * 4 + k4;
#pragma unroll
            for (int nt = 0; nt < 8; nt++) {
                int n = warp_n * 64 + nt * 8 + r;
                uint4 bv = g_WinP[(n * 16 + kf) * 4 + cq];
#pragma unroll
                for (int mt = 0; mt < 2; mt++) {
                    MMA_BF16(C[mt][nt], ah[mt][0], ah[mt][1], ah[mt][2], ah[mt][3], bv.x, bv.y);
                    MMA_BF16(C[mt][nt], ah[mt][0], ah[mt][1], ah[mt][2], ah[mt][3], bv.z, bv.w);
                    MMA_BF16(C[mt][nt], al[mt][0], al[mt][1], al[mt][2], al[mt][3], bv.x, bv.y);
                }
            }
        }
    }

    // LN + tanh epilogue -> Xh/Xl
    __syncthreads();
#pragma unroll
    for (int mt = 0; mt < 2; mt++) {
        float sA = 0.f, qA = 0.f, sB = 0.f, qB = 0.f;
#pragma unroll
        for (int nt = 0; nt < 8; nt++) {
            sA += C[mt][nt][0] + C[mt][nt][1];
            qA += C[mt][nt][0] * C[mt][nt][0] + C[mt][nt][1] * C[mt][nt][1];
            sB += C[mt][nt][2] + C[mt][nt][3];
            qB += C[mt][nt][2] * C[mt][nt][2] + C[mt][nt][3] * C[mt][nt][3];
        }
#pragma unroll
        for (int m = 1; m <= 2; m <<= 1) {
            sA += __shfl_xor_sync(0xffffffffu, sA, m);
            qA += __shfl_xor_sync(0xffffffffu, qA, m);
            sB += __shfl_xor_sync(0xffffffffu, sB, m);
            qB += __shfl_xor_sync(0xffffffffu, qB, m);
        }
        if (cq == 0) {
            int rowA = warp_m * 32 + mt * 16 + r;
            red[rowA * 2 + warp_n] = make_float2(sA, qA);
            red[(rowA + 8) * 2 + warp_n] = make_float2(sB, qB);
        }
    }
    __syncthreads();

    float muv[2][2], rsv[2][2];
#pragma unroll
    for (int mt = 0; mt < 2; mt++)
#pragma unroll
        for (int hb = 0; hb < 2; hb++) {
            int row = warp_m * 32 + mt * 16 + r + hb * 8;
            float2 p0 = red[row * 2 + 0], p1 = red[row * 2 + 1];
            float s = p0.x + p1.x, q = p0.y + p1.y;
            float mu = s * (1.0f / 128.0f);
            float var = q * (1.0f / 128.0f) - mu * mu;
            muv[mt][hb] = mu;
            rsv[mt][hb] = rsqrtf(var + LN_EPS);
        }

#pragma unroll
    for (int mt = 0; mt < 2; mt++) {
#pragma unroll
        for (int nt = 0; nt < 8; nt++) {
            int col = warp_n * 64 + nt * 8 + 2 * cq;
            int c2 = warp_n * 32 + nt * 4 + cq;
            float g0 = sgam[col], g1 = sgam[col + 1];
            float b0 = sbet[col], b1 = sbet[col + 1];
            int rowA = warp_m * 32 + mt * 16 + r;
#pragma unroll
            for (int hb = 0; hb < 2; hb++) {
                float x0 = tanh_f((C[mt][nt][2 * hb] - muv[mt][hb]) * rsv[mt][hb] * g0 + b0);
                float x1 = tanh_f((C[mt][nt][2 * hb + 1] - muv[mt][hb]) * rsv[mt][hb] * g1 + b1);
                __nv_bfloat16 h0 = __float2bfloat16(x0);
                __nv_bfloat16 h1 = __float2bfloat16(x1);
                __nv_bfloat162 hv; hv.x = h0; hv.y = h1;
                __nv_bfloat162 lv;
                lv.x = __float2bfloat16(x0 - __bfloat162float(h0));
                lv.y = __float2bfloat16(x1 - __bfloat162float(h1));
                Xh2[(rowA + hb * 8) * 68 + c2] = hv;
                Xl2[(rowA + hb * 8) * 68 + c2] = lv;
            }
        }
    }
    __syncthreads();

    // phase 2
    for (int pass = 0; pass < 8; pass++) {
        float D[2][4][4];
#pragma unroll
        for (int mt = 0; mt < 2; mt++)
#pragma unroll
            for (int nt = 0; nt < 4; nt++)
#pragma unroll
                for (int v = 0; v < 4; v++) D[mt][nt][v] = 0.0f;

#pragma unroll
        for (int k = 0; k < 8; k++) {
            uint32_t ah[2][4], al[2][4];
#pragma unroll
            for (int mt = 0; mt < 2; mt++) {
                LDSM_X4(ah[mt][0], ah[mt][1], ah[mt][2], ah[mt][3], aXh[mt] + k * 32);
                LDSM_X4(al[mt][0], al[mt][1], al[mt][2], al[mt][3], aXl[mt] + k * 32);
            }
#pragma unroll
            for (int nt = 0; nt < 4; nt++) {
                int n = pass * 64 + warp_n * 32 + nt * 8 + r;
                uint4 bv = g_WihP[(n * 8 + k) * 4 + cq];
#pragma unroll
                for (int mt = 0; mt < 2; mt++) {
                    MMA_BF16(D[mt][nt], ah[mt][0], ah[mt][1], ah[mt][2], ah[mt][3], bv.x, bv.y);
                    MMA_BF16(D[mt][nt], ah[mt][0], ah[mt][1], ah[mt][2], ah[mt][3], bv.z, bv.w);
                    MMA_BF16(D[mt][nt], al[mt][0], al[mt][1], al[mt][2], al[mt][3], bv.x, bv.y);
                }
            }
        }
#pragma unroll
        for (int mt = 0; mt < 2; mt++) {
#pragma unroll
            for (int nt = 0; nt < 4; nt++) {
                int col = pass * 64 + warp_n * 32 + nt * 8 + 2 * cq;
                float2 bb = *(const float2*)&sbias[col];
                int rowA = warp_m * 32 + mt * 16 + r;
                if (base + rowA < nrows) {
                    float2 o = make_float2(D[mt][nt][0] + bb.x, D[mt][nt][1] + bb.y);
                    *(float2*)&g_gi[(size_t)srow[rowA] * G4 + col] = o;
                }
                int rowB = rowA + 8;
                if (base + rowB < nrows) {
                    float2 o = make_float2(D[mt][nt][2] + bb.x, D[mt][nt][3] + bb.y);
                    *(float2*)&g_gi[(size_t)srow[rowB] * G4 + col] = o;
                }
            }
        }
    }
}

// ---------------- kernel 2: LSTM recurrence v5 — HMMA + gi prefetch ----------------
// Same as v4b but g_gi loads for timestep t are issued BEFORE the MMA chain,
// hiding L2/DRAM latency behind tensor work.
#define HSTRIDE 136
__global__ void __launch_bounds__(256) k_lstm(const int* __restrict__ lens) {
    __shared__ __nv_bfloat16 Hh[16 * HSTRIDE];
    __shared__ __nv_bfloat16 Hl[16 * HSTRIDE];
    __shared__ int ln_s[16];
    __shared__ int sp_s[16];
    __shared__ int maxlen_s;

    const int tid = threadIdx.x;
    const int lane = tid & 31, wid = tid >> 5;
    const int s = wid * 16;
    const int r = lane >> 2, cq = lane & 3;
    const int Lrow = ((lane >> 3) & 1) * 8 + (lane & 7);
    const int Lk8 = (lane >> 4) * 8;
    const int n0 = blockIdx.x * 16;

#pragma unroll
    for (int q = 0; q < 5; q++) {
        int idx = tid + q * 256;
        if (idx < 16 * HSTRIDE / 2) {
            ((uint32_t*)Hh)[idx] = 0u;
            ((uint32_t*)Hl)[idx] = 0u;
        }
    }
    if (tid < 16) {
        int pid = g_perm[n0 + tid];
        sp_s[tid] = pid;
        ln_s[tid] = lens[pid];
    }
    __syncthreads();
    if (tid == 0) {
        int m = 0;
#pragma unroll
        for (int i = 0; i < 16; i++) m = max(m, ln_s[i]);
        maxlen_s = m;
    }
    __syncthreads();

    int mylen[2], mypid[2];
#pragma unroll
    for (int rr = 0; rr < 2; rr++) {
        int pI = rr * 8 + r;
        mylen[rr] = ln_s[pI];
        mypid[rr] = sp_s[pI];
    }
    const int blkmax = maxlen_s;

    const uint32_t aH = smem_u32(Hh) + (Lrow * HSTRIDE + Lk8) * 2;
    const uint32_t aL = smem_u32(Hl) + (Lrow * HSTRIDE + Lk8) * 2;

    float cst[2][2][2];   // [rr][j][col01]
#pragma unroll
    for (int a = 0; a < 2; a++)
#pragma unroll
        for (int b = 0; b < 2; b++) { cst[a][b][0] = 0.f; cst[a][b][1] = 0.f; }

    for (int t = 0; t < blkmax; t++) {
        // ---- prefetch g_gi for this timestep BEFORE the MMA chain ----
        float2 pg[2][2][4];   // [rr][j][gate]
#pragma unroll
        for (int rr = 0; rr < 2; rr++) {
            if (t < mylen[rr]) {
                size_t rowb = ((size_t)mypid[rr] * LMAX + t) * G4;
#pragma unroll
                for (int j = 0; j < 2; j++) {
                    const int colg = s + j * 8 + 2 * cq;
#pragma unroll
                    for (int q = 0; q < 4; q++)
                        pg[rr][j][q] = *(const float2*)&g_gi[rowb + q * 128 + colg];
                }
            }
        }

        float C[2][4][4];   // [j][gate][v]
#pragma unroll
        for (int j = 0; j < 2; j++)
#pragma unroll
            for (int q = 0; q < 4; q++)
#pragma unroll
                for (int v = 0; v < 4; v++) C[j][q][v] = 0.0f;

#pragma unroll
        for (int kf = 0; kf < 8; kf++) {
            uint32_t ah[4], al[4];
            LDSM_X4(ah[0], ah[1], ah[2], ah[3], aH + kf * 32);
            LDSM_X4(al[0], al[1], al[2], al[3], aL + kf * 32);
#pragma unroll
            for (int j = 0; j < 2; j++) {
#pragma unroll
                for (int q = 0; q < 4; q++) {
                    int n = q * 128 + s + j * 8 + r;
                    uint4 bv = g_WhhP[(n * 8 + kf) * 4 + cq];
                    MMA_BF16(C[j][q], ah[0], ah[1], ah[2], ah[3], bv.x, bv.y);
                    MMA_BF16(C[j][q], ah[0], ah[1], ah[2], ah[3], bv.z, bv.w);
                    MMA_BF16(C[j][q], al[0], al[1], al[2], al[3], bv.x, bv.y);
                }
            }
        }
        __syncthreads();   // ALL h reads complete before any h write

#pragma unroll
        for (int j = 0; j < 2; j++) {
            const int colg = s + j * 8 + 2 * cq;
#pragma unroll
            for (int rr = 0; rr < 2; rr++) {
                if (t < mylen[rr]) {
                    float2 gi = pg[rr][j][0];
                    float2 gf = pg[rr][j][1];
                    float2 gg = pg[rr][j][2];
                    float2 go = pg[rr][j][3];
                    int v0 = rr * 2;
                    float xi0 = gi.x + C[j][0][v0], xi1 = gi.y + C[j][0][v0 + 1];
                    float xf0 = gf.x + C[j][1][v0], xf1 = gf.y + C[j][1][v0 + 1];
                    float xg0 = gg.x + C[j][2][v0], xg1 = gg.y + C[j][2][v0 + 1];
                    float xo0 = go.x + C[j][3][v0], xo1 = go.y + C[j][3][v0 + 1];
                    float cn0 = sigm_f(xf0) * cst[rr][j][0] + sigm_f(xi0) * tanh_f(xg0);
                    float cn1 = sigm_f(xf1) * cst[rr][j][1] + sigm_f(xi1) * tanh_f(xg1);
                    cst[rr][j][0] = cn0;
                    cst[rr][j][1] = cn1;
                    float h0 = sigm_f(xo0) * tanh_f(cn0);
                    float h1 = sigm_f(xo1) * tanh_f(cn1);
                    __nv_bfloat16 b0 = __float2bfloat16(h0);
                    __nv_bfloat16 b1 = __float2bfloat16(h1);
                    __nv_bfloat162 hv; hv.x = b0; hv.y = b1;
                    __nv_bfloat162 lv;
                    lv.x = __float2bfloat16(h0 - __bfloat162float(b0));
                    lv.y = __float2bfloat16(h1 - __bfloat162float(b1));
                    int pI = rr * 8 + r;
                    *(__nv_bfloat162*)&Hh[pI * HSTRIDE + colg] = hv;
                    *(__nv_bfloat162*)&Hl[pI * HSTRIDE + colg] = lv;
                }
            }
        }
        __syncthreads();
    }

    // final h: g_h[pid][k] = hi + lo
#pragma unroll
    for (int q = 0; q < 8; q++) {
        int idx = tid + q * 256;
        int n = idx >> 7, k = idx & 127;
        g_h[(size_t)sp_s[n] * HDIM + k] =
            __bfloat162float(Hh[n * HSTRIDE + k]) + __bfloat162float(Hl[n * HSTRIDE + k]);
    }
}

// ---------------- kernel 3a: init accumulators (+ counters) ----------------
__global__ void k_init() {
    int i = blockIdx.x * blockDim.x + threadIdx.x;
    if (i < GRP * HDIM) g_wsum[i] = 0.0f;
    if (i < GRP) {
        g_gsum[i] = 0.0f;
        g_cnt[i] = 0.0f;
        g_gmax[i] = 0u;
    }
    if (i < 40) g_lcnt[i] = 0;
    if (i == 0) g_nrows = 0;
}

// ---------------- kernel 3b: attention logits + segment max ----------------
__global__ void __launch_bounds__(256) k_logits(const float* __restrict__ ap,
                                                const int* __restrict__ seg) {
    int w = threadIdx.x >> 5, lane = threadIdx.x & 31;
    int n = blockIdx.x * 8 + w;
    float s = 0.0f;
#pragma unroll
    for (int q = 0; q < 4; q++) s += g_h[n * HDIM + lane + 32 * q] * ap[lane + 32 * q];
#pragma unroll
    for (int m = 16; m >= 1; m >>= 1) s += __shfl_xor_sync(0xffffffffu, s, m);
    if (lane == 0) {
        g_logits[n] = s;
        atomicMax(&g_gmax[seg[n]], enc_f(s));
    }
}

// ---------------- kernel 3c: exp + segment sum + count ----------------
__global__ void __launch_bounds__(256) k_expsum(const int* __restrict__ seg) {
    int n = blockIdx.x * 256 + threadIdx.x;
    int g = seg[n];
    float e = expf(g_logits[n] - dec_f(g_gmax[g]));
    g_e[n] = e;
    atomicAdd(&g_gsum[g], e);
    atomicAdd(&g_cnt[g], 1.0f);
}

// ---------------- kernel 3d: weighted hidden sum per group ----------------
__global__ void __launch_bounds__(256) k_wsum(const int* __restrict__ seg) {
    int w = threadIdx.x >> 5, lane = threadIdx.x & 31;
    int n = blockIdx.x * 8 + w;
    float e = g_e[n];
    int g = seg[n];
#pragma unroll
    for (int q = 0; q < 4; q++)
        atomicAdd(&g_wsum[g * HDIM + lane + 32 * q], e * g_h[n * HDIM + lane + 32 * q]);
}

// ---------------- kernel 4: head ----------------
__global__ void __launch_bounds__(256) k_head(const float* __restrict__ W_out,
                                              const float* __restrict__ W_cls,
                                              const float* __restrict__ ap,
                                              float* __restrict__ out,
                                              int out_size) {
    __shared__ float cs[16 * 128];
    __shared__ float cvs[16 * 128];
    const int tid = threadIdx.x;
    const int g0 = blockIdx.x * 16;
    const bool full = (out_size >= 2048 + GRP * HDIM + HDIM);

#pragma unroll
    for (int s = 0; s < 8; s++) {
        int idx = tid + s * 256;
        int gg = idx >> 7, k = idx & 127;
        int gi = g0 + gg;
        cs[gg * 128 + k] = g_wsum[gi * HDIM + k] / (g_gsum[gi] * g_cnt[gi]);
    }
    __syncthreads();

    int row = tid >> 4;
    int c0 = (tid & 15) * 8;
    float acc[8];
#pragma unroll
    for (int j = 0; j < 8; j++) acc[j] = 0.0f;
    for (int k = 0; k < 128; k++) {
        float a = cs[row * 128 + k];
#pragma unroll
        for (int j = 0; j < 8; j++) acc[j] += a * W_out[(c0 + j) * 128 + k];
    }
#pragma unroll
    for (int j = 0; j < 8; j++) {
        cvs[row * 128 + c0 + j] = acc[j];
        if (full) out[2048 + (g0 + row) * 128 + c0 + j] = acc[j];
    }
    __syncthreads();

    if (tid < 32) {
        int rr = tid >> 1, cc = tid & 1;
        float s = 0.0f;
        for (int k = 0; k < 128; k++) s += cvs[rr * 128 + k] * W_cls[cc * 128 + k];
        out[(g0 + rr) * 2 + cc] = s;
    }
    if (full && blockIdx.x == 0 && tid < 128) out[2048 + GRP * HDIM + tid] = ap[tid];
}

// ---------------- launch ----------------
extern "C" void kernel_launch(void* const* d_in, const int* in_sizes, int n_in,
                              void* d_out, int out_size) {
    const float* inputs = (const float*)d_in[0];
    const int* lens     = (const int*)d_in[1];
    const int* seg      = (const int*)d_in[2];
    const float* W_in   = (const float*)d_in[3];
    const float* gamma  = (const float*)d_in[4];
    const float* beta   = (const float*)d_in[5];
    const float* Wih    = (const float*)d_in[6];
    const float* Whh    = (const float*)d_in[7];
    const float* bih    = (const float*)d_in[8];
    const float* bhh    = (const float*)d_in[9];
    const float* ap     = (const float*)d_in[10];
    const float* W_out  = (const float*)d_in[11];
    const float* W_cls  = (const float*)d_in[12];
    float* out = (float*)d_out;

    const int fp_smem = FP_SMEM_B32 * 4;   // 112128 B
    cudaFuncSetAttribute(k_fp, cudaFuncAttributeMaxDynamicSharedMemorySize, fp_smem);

    k_init<<<(GRP * HDIM + 255) / 256, 256>>>();
    k_rowlist<<<NPATH / 256, 256>>>(lens);
    k_prep<<<160, 256>>>(W_in, Wih, Whh);
    k_fp<<<RTOT / 128, 256, fp_smem>>>(inputs, gamma, beta, bih, bhh);
    k_hist<<<NPATH / 256, 256>>>(lens);
    k_scan<<<1, 32>>>();
    k_scatter<<<NPATH / 256, 256>>>(lens);
    k_lstm<<<NPATH / 16, 256>>>(lens);
    k_logits<<<NPATH / 8, 256>>>(ap, seg);
    k_expsum<<<NPATH / 256, 256>>>(seg);
    k_wsum<<<NPATH / 8, 256>>>(seg);
    k_head<<<GRP / 16, 256>>>(W_out, W_cls, ap, out, out_size);
}

// round 17
// speedup vs baseline: 1.0258x; 1.0258x over previous
#include <cuda_runtime.h>
#include <cuda_bf16.h>
#include <cstdint>

#define NPATH 8192
#define LMAX 32
#define DIN 256
#define EDIM 128
#define HDIM 128
#define G4 512
#define GRP 1024
#define RTOT (NPATH*LMAX)
#define LN_EPS 1e-5f

typedef unsigned long long ull;

// ---------------- device scratch (static, no allocation) ----------------
__device__ float g_gi[(size_t)RTOT*G4]; // 512 MB
__device__ uint4 g_WinP[EDIM*16*4];     // [(n*16+kf)*4+cq] = {bh0,bh1,bl0,bl1}
__device__ uint4 g_WihP[G4*8*4];        // [(n*8+kf)*4+cq]
__device__ uint4 g_WhhP[G4*8*4];        // [(n*8+kf)*4+cq]
__device__ float g_h[NPATH*HDIM];
__device__ float g_logits[NPATH];
__device__ float g_e[NPATH];
__device__ unsigned g_gmax[GRP];
__device__ float g_gsum[GRP];
__device__ float g_cnt[GRP];
__device__ float g_wsum[GRP*HDIM];
__device__ int g_lcnt[40];
__device__ int g_lstart[40];
__device__ int g_perm[NPATH];
__device__ int g_nrows;
__device__ int g_rows[RTOT];

// ---------------- fast activations (clamped, ~1e-6 rel err) ----------------
__device__ __forceinline__ float sigm_f(float x) {
    x = fmaxf(fminf(x, 30.0f), -30.0f);
    return __fdividef(1.0f, 1.0f + __expf(-x));
}
__device__ __forceinline__ float tanh_f(float x) {
    x = fmaxf(fminf(x, 15.0f), -15.0f);
    float e = __expf(-2.0f * x);
    return __fdividef(1.0f - e, 1.0f + e);
}

__device__ __forceinline__ unsigned enc_f(float f) {
    unsigned u = __float_as_uint(f);
    return (u & 0x80000000u) ? ~u : (u | 0x80000000u);
}
__device__ __forceinline__ float dec_f(unsigned k) {
    return (k & 0x80000000u) ? __uint_as_float(k ^ 0x80000000u) : __uint_as_float(~k);
}

// ---------------- mma / ldmatrix helpers ----------------
#define MMA_BF16(Cr, a0, a1, a2, a3, b0, b1) \
    asm volatile("mma.sync.aligned.m16n8k16.row.col.f32.bf16.bf16.f32 " \
        "{%0,%1,%2,%3}, {%4,%5,%6,%7}, {%8,%9}, {%0,%1,%2,%3};" \
        : "+f"((Cr)[0]), "+f"((Cr)[1]), "+f"((Cr)[2]), "+f"((Cr)[3]) \
        : "r"(a0), "r"(a1), "r"(a2), "r"(a3), "r"(b0), "r"(b1))

#define LDSM_X4(r0, r1, r2, r3, a) \
    asm volatile("ldmatrix.sync.aligned.m8n8.x4.shared.b16 {%0,%1,%2,%3}, [%4];" \
        : "=r"(r0), "=r"(r1), "=r"(r2), "=r"(r3) : "r"(a))

__device__ __forceinline__ uint32_t smem_u32(const void* p) {
    uint32_t a;
    asm("{ .reg .u64 t; cvta.to.shared.u64 t, %1; cvt.u32.u64 %0, t; }" : "=r"(a) : "l"(p));
    return a;
}
__device__ __forceinline__ uint32_t bf2_pack(float x, float y) {
    __nv_bfloat162 v;
    v.x = __float2bfloat16(x);
    v.y = __float2bfloat16(y);
    return *(uint32_t*)&v;
}

// ---------------- sort kernels ----------------
__global__ void k_histrow(const int* __restrict__ lens) {
    int n = blockIdx.x * 256 + threadIdx.x;
    if (n < NPATH) {
        int l = lens[n];
        atomicAdd(&g_lcnt[l], 1);
        int pos = atomicAdd(&g_nrows, l);
        int base = n * LMAX;
        for (int t = 0; t < l; t++) g_rows[pos + t] = base + t;
    }
}
__global__ void k_scan() {
    if (threadIdx.x == 0 && blockIdx.x == 0) {
        int run = 0;
        for (int l = LMAX; l >= 1; l--) { g_lstart[l] = run; run += g_lcnt[l]; }
    }
}
__global__ void k_scatter(const int* __restrict__ lens) {
    int n = blockIdx.x * 256 + threadIdx.x;
    if (n < NPATH) {
        int pos = atomicAdd(&g_lstart[lens[n]], 1);
        g_perm[pos] = n;
    }
}

// ---------------- kernel 0: fragment-pack all weights (fp32 -> bf16 hi/lo uint4) ----------------
__device__ __forceinline__ uint4 pack_frag(const float* __restrict__ W, int e) {
    float a0 = W[e], a1 = W[e + 1], a2 = W[e + 8], a3 = W[e + 9];
    __nv_bfloat16 h0 = __float2bfloat16(a0), h1 = __float2bfloat16(a1);
    __nv_bfloat16 h2 = __float2bfloat16(a2), h3 = __float2bfloat16(a3);
    uint4 v;
    v.x = bf2_pack(a0, a1);
    v.y = bf2_pack(a2, a3);
    v.z = bf2_pack(a0 - __bfloat162float(h0), a1 - __bfloat162float(h1));
    v.w = bf2_pack(a2 - __bfloat162float(h2), a3 - __bfloat162float(h3));
    return v;
}
__global__ void __launch_bounds__(256) k_prep(const float* __restrict__ W_in,
                                              const float* __restrict__ Wih,
                                              const float* __restrict__ Whh) {
    int idx = blockIdx.x * 256 + threadIdx.x;   // 40960 total
    if (idx < 8192) {
        int cq = idx & 3, kf = (idx >> 2) & 15, n = idx >> 6;
        g_WinP[idx] = pack_frag(W_in, n * DIN + kf * 16 + 2 * cq);
    } else if (idx < 24576) {
        int i2 = idx - 8192;
        int cq = i2 & 3, kf = (i2 >> 2) & 7, n = i2 >> 5;
        g_WihP[i2] = pack_frag(Wih, n * HDIM + kf * 16 + 2 * cq);
    } else if (idx < 40960) {
        int i2 = idx - 24576;
        int cq = i2 & 3, kf = (i2 >> 2) & 7, n = i2 >> 5;
        g_WhhP[i2] = pack_frag(Whh, n * HDIM + kf * 16 + 2 * cq);
    }
}

// smem offsets (b32 units) for k_fp
#define OFF_AH   0
#define OFF_AL   4608
#define OFF_XH   9216
#define OFF_XL   17920
#define OFF_RED  26624
#define OFF_GAM  27136
#define OFF_BET  27264
#define OFF_BIAS 27392
#define OFF_SROW 27904
#define FP_SMEM_B32 28032

// ---------------- kernel 1: mma-based fused projection+LN+tanh + gate GEMM ----------------
__global__ void __launch_bounds__(256, 2) k_fp(const float* __restrict__ inp,
                                               const float* __restrict__ gamma,
                                               const float* __restrict__ beta,
                                               const float* __restrict__ bih,
                                               const float* __restrict__ bhh) {
    extern __shared__ uint32_t s32[];
    __nv_bfloat16* Ah16 = (__nv_bfloat16*)(s32 + OFF_AH);
    __nv_bfloat16* Al16 = (__nv_bfloat16*)(s32 + OFF_AL);
    __nv_bfloat162* Xh2 = (__nv_bfloat162*)(s32 + OFF_XH);
    __nv_bfloat162* Xl2 = (__nv_bfloat162*)(s32 + OFF_XL);
    float2* red = (float2*)(s32 + OFF_RED);
    float* sgam = (float*)(s32 + OFF_GAM);
    float* sbet = (float*)(s32 + OFF_BET);
    float* sbias = (float*)(s32 + OFF_BIAS);
    int* srow = (int*)(s32 + OFF_SROW);

    const int tid = threadIdx.x;
    const int lane = tid & 31, wid = tid >> 5;
    const int warp_m = wid & 3, warp_n = wid >> 2;
    const int r = lane >> 2, cq = lane & 3;
    const int base = blockIdx.x * 128;
    const int nrows = g_nrows;
    if (base >= nrows) return;

    const int Lrow = ((lane >> 3) & 1) * 8 + (lane & 7);
    const int Lk8 = (lane >> 4) * 8;

    if (tid < 128) {
        srow[tid] = (base + tid < nrows) ? g_rows[base + tid] : g_rows[base];
        sgam[tid] = gamma[tid];
        sbet[tid] = beta[tid];
    }
    sbias[tid] = bih[tid] + bhh[tid];
    sbias[tid + 256] = bih[tid + 256] + bhh[tid + 256];
    __syncthreads();

    uint32_t aAh[2], aAl[2], aXh[2], aXl[2];
#pragma unroll
    for (int mt = 0; mt < 2; mt++) {
        int row = warp_m * 32 + mt * 16 + Lrow;
        aAh[mt] = smem_u32(Ah16) + (row * 72 + Lk8) * 2;
        aAl[mt] = smem_u32(Al16) + (row * 72 + Lk8) * 2;
        aXh[mt] = smem_u32(Xh2) + row * 68 * 4 + Lk8 * 2;
        aXl[mt] = smem_u32(Xl2) + row * 68 * 4 + Lk8 * 2;
    }

    // phase 1
    float C[2][8][4];
#pragma unroll
    for (int mt = 0; mt < 2; mt++)
#pragma unroll
        for (int nt = 0; nt < 8; nt++)
#pragma unroll
            for (int v = 0; v < 4; v++) C[mt][nt][v] = 0.0f;

    for (int ks = 0; ks < 4; ks++) {
        __syncthreads();
#pragma unroll
        for (int s = 0; s < 32; s++) {
            int idx = tid + s * 256;
            int row = idx >> 6, c = idx & 63;
            float v = inp[(size_t)srow[row] * DIN + ks * 64 + c];
            __nv_bfloat16 h = __float2bfloat16(v);
            Ah16[row * 72 + c] = h;
            Al16[row * 72 + c] = __float2bfloat16(v - __bfloat162float(h));
        }
        __syncthreads();
#pragma unroll
        for (int k4 = 0; k4 < 4; k4++) {
            uint32_t ah[2][4], al[2][4];
#pragma unroll
            for (int mt = 0; mt < 2; mt++) {
                LDSM_X4(ah[mt][0], ah[mt][1], ah[mt][2], ah[mt][3], aAh[mt] + k4 * 32);
                LDSM_X4(al[mt][0], al[mt][1], al[mt][2], al[mt][3], aAl[mt] + k4 * 32);
            }
            const int kf = ks * 4 + k4;
#pragma unroll
            for (int nt = 0; nt < 8; nt++) {
                int n = warp_n * 64 + nt * 8 + r;
                uint4 bv = g_WinP[(n * 16 + kf) * 4 + cq];
#pragma unroll
                for (int mt = 0; mt < 2; mt++) {
                    MMA_BF16(C[mt][nt], ah[mt][0], ah[mt][1], ah[mt][2], ah[mt][3], bv.x, bv.y);
                    MMA_BF16(C[mt][nt], ah[mt][0], ah[mt][1], ah[mt][2], ah[mt][3], bv.z, bv.w);
                    MMA_BF16(C[mt][nt], al[mt][0], al[mt][1], al[mt][2], al[mt][3], bv.x, bv.y);
                }
            }
        }
    }

    // LN + tanh epilogue -> Xh/Xl
    __syncthreads();
#pragma unroll
    for (int mt = 0; mt < 2; mt++) {
        float sA = 0.f, qA = 0.f, sB = 0.f, qB = 0.f;
#pragma unroll
        for (int nt = 0; nt < 8; nt++) {
            sA += C[mt][nt][0] + C[mt][nt][1];
            qA += C[mt][nt][0] * C[mt][nt][0] + C[mt][nt][1] * C[mt][nt][1];
            sB += C[mt][nt][2] + C[mt][nt][3];
            qB += C[mt][nt][2] * C[mt][nt][2] + C[mt][nt][3] * C[mt][nt][3];
        }
#pragma unroll
        for (int m = 1; m <= 2; m <<= 1) {
            sA += __shfl_xor_sync(0xffffffffu, sA, m);
            qA += __shfl_xor_sync(0xffffffffu, qA, m);
            sB += __shfl_xor_sync(0xffffffffu, sB, m);
            qB += __shfl_xor_sync(0xffffffffu, qB, m);
        }
        if (cq == 0) {
            int rowA = warp_m * 32 + mt * 16 + r;
            red[rowA * 2 + warp_n] = make_float2(sA, qA);
            red[(rowA + 8) * 2 + warp_n] = make_float2(sB, qB);
        }
    }
    __syncthreads();

    float muv[2][2], rsv[2][2];
#pragma unroll
    for (int mt = 0; mt < 2; mt++)
#pragma unroll
        for (int hb = 0; hb < 2; hb++) {
            int row = warp_m * 32 + mt * 16 + r + hb * 8;
            float2 p0 = red[row * 2 + 0], p1 = red[row * 2 + 1];
            float s = p0.x + p1.x, q = p0.y + p1.y;
            float mu = s * (1.0f / 128.0f);
            float var = q * (1.0f / 128.0f) - mu * mu;
            muv[mt][hb] = mu;
            rsv[mt][hb] = rsqrtf(var + LN_EPS);
        }

#pragma unroll
    for (int mt = 0; mt < 2; mt++) {
#pragma unroll
        for (int nt = 0; nt < 8; nt++) {
            int col = warp_n * 64 + nt * 8 + 2 * cq;
            int c2 = warp_n * 32 + nt * 4 + cq;
            float g0 = sgam[col], g1 = sgam[col + 1];
            float b0 = sbet[col], b1 = sbet[col + 1];
            int rowA = warp_m * 32 + mt * 16 + r;
#pragma unroll
            for (int hb = 0; hb < 2; hb++) {
                float x0 = tanh_f((C[mt][nt][2 * hb] - muv[mt][hb]) * rsv[mt][hb] * g0 + b0);
                float x1 = tanh_f((C[mt][nt][2 * hb + 1] - muv[mt][hb]) * rsv[mt][hb] * g1 + b1);
                __nv_bfloat16 h0 = __float2bfloat16(x0);
                __nv_bfloat16 h1 = __float2bfloat16(x1);
                __nv_bfloat162 hv; hv.x = h0; hv.y = h1;
                __nv_bfloat162 lv;
                lv.x = __float2bfloat16(x0 - __bfloat162float(h0));
                lv.y = __float2bfloat16(x1 - __bfloat162float(h1));
                Xh2[(rowA + hb * 8) * 68 + c2] = hv;
                Xl2[(rowA + hb * 8) * 68 + c2] = lv;
            }
        }
    }
    __syncthreads();

    // phase 2 (B fragments double-buffered across k)
    for (int pass = 0; pass < 8; pass++) {
        float D[2][4][4];
#pragma unroll
        for (int mt = 0; mt < 2; mt++)
#pragma unroll
            for (int nt = 0; nt < 4; nt++)
#pragma unroll
                for (int v = 0; v < 4; v++) D[mt][nt][v] = 0.0f;

        const int nb = pass * 64 + warp_n * 32 + r;
        uint4 bvn[4];
#pragma unroll
        for (int nt = 0; nt < 4; nt++)
            bvn[nt] = g_WihP[((nb + nt * 8) * 8 + 0) * 4 + cq];

#pragma unroll
        for (int k = 0; k < 8; k++) {
            uint4 bv[4];
#pragma unroll
            for (int nt = 0; nt < 4; nt++) bv[nt] = bvn[nt];
            if (k < 7) {
#pragma unroll
                for (int nt = 0; nt < 4; nt++)
                    bvn[nt] = g_WihP[((nb + nt * 8) * 8 + k + 1) * 4 + cq];
            }
            uint32_t ah[2][4], al[2][4];
#pragma unroll
            for (int mt = 0; mt < 2; mt++) {
                LDSM_X4(ah[mt][0], ah[mt][1], ah[mt][2], ah[mt][3], aXh[mt] + k * 32);
                LDSM_X4(al[mt][0], al[mt][1], al[mt][2], al[mt][3], aXl[mt] + k * 32);
            }
#pragma unroll
            for (int nt = 0; nt < 4; nt++) {
#pragma unroll
                for (int mt = 0; mt < 2; mt++) {
                    MMA_BF16(D[mt][nt], ah[mt][0], ah[mt][1], ah[mt][2], ah[mt][3], bv[nt].x, bv[nt].y);
                    MMA_BF16(D[mt][nt], ah[mt][0], ah[mt][1], ah[mt][2], ah[mt][3], bv[nt].z, bv[nt].w);
                    MMA_BF16(D[mt][nt], al[mt][0], al[mt][1], al[mt][2], al[mt][3], bv[nt].x, bv[nt].y);
                }
            }
        }
#pragma unroll
        for (int mt = 0; mt < 2; mt++) {
#pragma unroll
            for (int nt = 0; nt < 4; nt++) {
                int col = pass * 64 + warp_n * 32 + nt * 8 + 2 * cq;
                float2 bb = *(const float2*)&sbias[col];
                int rowA = warp_m * 32 + mt * 16 + r;
                if (base + rowA < nrows) {
                    float2 o = make_float2(D[mt][nt][0] + bb.x, D[mt][nt][1] + bb.y);
                    *(float2*)&g_gi[(size_t)srow[rowA] * G4 + col] = o;
                }
                int rowB = rowA + 8;
                if (base + rowB < nrows) {
                    float2 o = make_float2(D[mt][nt][2] + bb.x, D[mt][nt][3] + bb.y);
                    *(float2*)&g_gi[(size_t)srow[rowB] * G4 + col] = o;
                }
            }
        }
    }
}

// ---------------- kernel 2: LSTM recurrence v4b — HMMA, 16 paths/block (R15 exact) ----------------
#define HSTRIDE 136
__global__ void __launch_bounds__(256) k_lstm(const int* __restrict__ lens) {
    __shared__ __nv_bfloat16 Hh[16 * HSTRIDE];
    __shared__ __nv_bfloat16 Hl[16 * HSTRIDE];
    __shared__ int ln_s[16];
    __shared__ int sp_s[16];
    __shared__ int maxlen_s;

    const int tid = threadIdx.x;
    const int lane = tid & 31, wid = tid >> 5;
    const int s = wid * 16;
    const int r = lane >> 2, cq = lane & 3;
    const int Lrow = ((lane >> 3) & 1) * 8 + (lane & 7);
    const int Lk8 = (lane >> 4) * 8;
    const int n0 = blockIdx.x * 16;

#pragma unroll
    for (int q = 0; q < 5; q++) {
        int idx = tid + q * 256;
        if (idx < 16 * HSTRIDE / 2) {
            ((uint32_t*)Hh)[idx] = 0u;
            ((uint32_t*)Hl)[idx] = 0u;
        }
    }
    if (tid < 16) {
        int pid = g_perm[n0 + tid];
        sp_s[tid] = pid;
        ln_s[tid] = lens[pid];
    }
    __syncthreads();
    if (tid == 0) {
        int m = 0;
#pragma unroll
        for (int i = 0; i < 16; i++) m = max(m, ln_s[i]);
        maxlen_s = m;
    }
    __syncthreads();

    int mylen[2], mypid[2];
#pragma unroll
    for (int rr = 0; rr < 2; rr++) {
        int pI = rr * 8 + r;
        mylen[rr] = ln_s[pI];
        mypid[rr] = sp_s[pI];
    }
    const int blkmax = maxlen_s;

    const uint32_t aH = smem_u32(Hh) + (Lrow * HSTRIDE + Lk8) * 2;
    const uint32_t aL = smem_u32(Hl) + (Lrow * HSTRIDE + Lk8) * 2;

    float cst[2][2][2];   // [rr][j][col01]
#pragma unroll
    for (int a = 0; a < 2; a++)
#pragma unroll
        for (int b = 0; b < 2; b++) { cst[a][b][0] = 0.f; cst[a][b][1] = 0.f; }

    for (int t = 0; t < blkmax; t++) {
        float C[2][4][4];   // [j][gate][v]
#pragma unroll
        for (int j = 0; j < 2; j++)
#pragma unroll
            for (int q = 0; q < 4; q++)
#pragma unroll
                for (int v = 0; v < 4; v++) C[j][q][v] = 0.0f;

#pragma unroll
        for (int kf = 0; kf < 8; kf++) {
            uint32_t ah[4], al[4];
            LDSM_X4(ah[0], ah[1], ah[2], ah[3], aH + kf * 32);
            LDSM_X4(al[0], al[1], al[2], al[3], aL + kf * 32);
#pragma unroll
            for (int j = 0; j < 2; j++) {
#pragma unroll
                for (int q = 0; q < 4; q++) {
                    int n = q * 128 + s + j * 8 + r;
                    uint4 bv = g_WhhP[(n * 8 + kf) * 4 + cq];
                    MMA_BF16(C[j][q], ah[0], ah[1], ah[2], ah[3], bv.x, bv.y);
                    MMA_BF16(C[j][q], ah[0], ah[1], ah[2], ah[3], bv.z, bv.w);
                    MMA_BF16(C[j][q], al[0], al[1], al[2], al[3], bv.x, bv.y);
                }
            }
        }
        __syncthreads();   // ALL h reads complete before any h write

#pragma unroll
        for (int j = 0; j < 2; j++) {
            const int colg = s + j * 8 + 2 * cq;
#pragma unroll
            for (int rr = 0; rr < 2; rr++) {
                if (t < mylen[rr]) {
                    size_t row = ((size_t)mypid[rr] * LMAX + t) * G4 + colg;
                    float2 gi = *(const float2*)&g_gi[row];
                    float2 gf = *(const float2*)&g_gi[row + 128];
                    float2 gg = *(const float2*)&g_gi[row + 256];
                    float2 go = *(const float2*)&g_gi[row + 384];
                    int v0 = rr * 2;
                    float xi0 = gi.x + C[j][0][v0], xi1 = gi.y + C[j][0][v0 + 1];
                    float xf0 = gf.x + C[j][1][v0], xf1 = gf.y + C[j][1][v0 + 1];
                    float xg0 = gg.x + C[j][2][v0], xg1 = gg.y + C[j][2][v0 + 1];
                    float xo0 = go.x + C[j][3][v0], xo1 = go.y + C[j][3][v0 + 1];
                    float cn0 = sigm_f(xf0) * cst[rr][j][0] + sigm_f(xi0) * tanh_f(xg0);
                    float cn1 = sigm_f(xf1) * cst[rr][j][1] + sigm_f(xi1) * tanh_f(xg1);
                    cst[rr][j][0] = cn0;
                    cst[rr][j][1] = cn1;
                    float h0 = sigm_f(xo0) * tanh_f(cn0);
                    float h1 = sigm_f(xo1) * tanh_f(cn1);
                    __nv_bfloat16 b0 = __float2bfloat16(h0);
                    __nv_bfloat16 b1 = __float2bfloat16(h1);
                    __nv_bfloat162 hv; hv.x = b0; hv.y = b1;
                    __nv_bfloat162 lv;
                    lv.x = __float2bfloat16(h0 - __bfloat162float(b0));
                    lv.y = __float2bfloat16(h1 - __bfloat162float(b1));
                    int pI = rr * 8 + r;
                    *(__nv_bfloat162*)&Hh[pI * HSTRIDE + colg] = hv;
                    *(__nv_bfloat162*)&Hl[pI * HSTRIDE + colg] = lv;
                }
            }
        }
        __syncthreads();
    }

    // final h: g_h[pid][k] = hi + lo
#pragma unroll
    for (int q = 0; q < 8; q++) {
        int idx = tid + q * 256;
        int n = idx >> 7, k = idx & 127;
        g_h[(size_t)sp_s[n] * HDIM + k] =
            __bfloat162float(Hh[n * HSTRIDE + k]) + __bfloat162float(Hl[n * HSTRIDE + k]);
    }
}

// ---------------- kernel 3a: init accumulators (+ counters) ----------------
__global__ void k_init() {
    int i = blockIdx.x * blockDim.x + threadIdx.x;
    if (i < GRP * HDIM) g_wsum[i] = 0.0f;
    if (i < GRP) {
        g_gsum[i] = 0.0f;
        g_cnt[i] = 0.0f;
        g_gmax[i] = 0u;
    }
    if (i < 40) g_lcnt[i] = 0;
    if (i == 0) g_nrows = 0;
}

// ---------------- kernel 3b: attention logits + segment max ----------------
__global__ void __launch_bounds__(256) k_logits(const float* __restrict__ ap,
                                                const int* __restrict__ seg) {
    int w = threadIdx.x >> 5, lane = threadIdx.x & 31;
    int n = blockIdx.x * 8 + w;
    float s = 0.0f;
#pragma unroll
    for (int q = 0; q < 4; q++) s += g_h[n * HDIM + lane + 32 * q] * ap[lane + 32 * q];
#pragma unroll
    for (int m = 16; m >= 1; m >>= 1) s += __shfl_xor_sync(0xffffffffu, s, m);
    if (lane == 0) {
        g_logits[n] = s;
        atomicMax(&g_gmax[seg[n]], enc_f(s));
    }
}

// ---------------- kernel 3c: exp + segment sum + count ----------------
__global__ void __launch_bounds__(256) k_expsum(const int* __restrict__ seg) {
    int n = blockIdx.x * 256 + threadIdx.x;
    int g = seg[n];
    float e = expf(g_logits[n] - dec_f(g_gmax[g]));
    g_e[n] = e;
    atomicAdd(&g_gsum[g], e);
    atomicAdd(&g_cnt[g], 1.0f);
}

// ---------------- kernel 3d: weighted hidden sum per group ----------------
__global__ void __launch_bounds__(256) k_wsum(const int* __restrict__ seg) {
    int w = threadIdx.x >> 5, lane = threadIdx.x & 31;
    int n = blockIdx.x * 8 + w;
    float e = g_e[n];
    int g = seg[n];
#pragma unroll
    for (int q = 0; q < 4; q++)
        atomicAdd(&g_wsum[g * HDIM + lane + 32 * q], e * g_h[n * HDIM + lane + 32 * q]);
}

// ---------------- kernel 4: head ----------------
__global__ void __launch_bounds__(256) k_head(const float* __restrict__ W_out,
                                              const float* __restrict__ W_cls,
                                              const float* __restrict__ ap,
                                              float* __restrict__ out,
                                              int out_size) {
    __shared__ float cs[16 * 128];
    __shared__ float cvs[16 * 128];
    const int tid = threadIdx.x;
    const int g0 = blockIdx.x * 16;
    const bool full = (out_size >= 2048 + GRP * HDIM + HDIM);

#pragma unroll
    for (int s = 0; s < 8; s++) {
        int idx = tid + s * 256;
        int gg = idx >> 7, k = idx & 127;
        int gi = g0 + gg;
        cs[gg * 128 + k] = g_wsum[gi * HDIM + k] / (g_gsum[gi] * g_cnt[gi]);
    }
    __syncthreads();

    int row = tid >> 4;
    int c0 = (tid & 15) * 8;
    float acc[8];
#pragma unroll
    for (int j = 0; j < 8; j++) acc[j] = 0.0f;
    for (int k = 0; k < 128; k++) {
        float a = cs[row * 128 + k];
#pragma unroll
        for (int j = 0; j < 8; j++) acc[j] += a * W_out[(c0 + j) * 128 + k];
    }
#pragma unroll
    for (int j = 0; j < 8; j++) {
        cvs[row * 128 + c0 + j] = acc[j];
        if (full) out[2048 + (g0 + row) * 128 + c0 + j] = acc[j];
    }
    __syncthreads();

    if (tid < 32) {
        int rr = tid >> 1, cc = tid & 1;
        float s = 0.0f;
        for (int k = 0; k < 128; k++) s += cvs[rr * 128 + k] * W_cls[cc * 128 + k];
        out[(g0 + rr) * 2 + cc] = s;
    }
    if (full && blockIdx.x == 0 && tid < 128) out[2048 + GRP * HDIM + tid] = ap[tid];
}

// ---------------- launch ----------------
extern "C" void kernel_launch(void* const* d_in, const int* in_sizes, int n_in,
                              void* d_out, int out_size) {
    const float* inputs = (const float*)d_in[0];
    const int* lens     = (const int*)d_in[1];
    const int* seg      = (const int*)d_in[2];
    const float* W_in   = (const float*)d_in[3];
    const float* gamma  = (const float*)d_in[4];
    const float* beta   = (const float*)d_in[5];
    const float* Wih    = (const float*)d_in[6];
    const float* Whh    = (const float*)d_in[7];
    const float* bih    = (const float*)d_in[8];
    const float* bhh    = (const float*)d_in[9];
    const float* ap     = (const float*)d_in[10];
    const float* W_out  = (const float*)d_in[11];
    const float* W_cls  = (const float*)d_in[12];
    float* out = (float*)d_out;

    const int fp_smem = FP_SMEM_B32 * 4;   // 112128 B
    cudaFuncSetAttribute(k_fp, cudaFuncAttributeMaxDynamicSharedMemorySize, fp_smem);

    k_init<<<(GRP * HDIM + 255) / 256, 256>>>();
    k_histrow<<<NPATH / 256, 256>>>(lens);
    k_prep<<<160, 256>>>(W_in, Wih, Whh);
    k_fp<<<RTOT / 128, 256, fp_smem>>>(inputs, gamma, beta, bih, bhh);
    k_scan<<<1, 32>>>();
    k_scatter<<<NPATH / 256, 256>>>(lens);
    k_lstm<<<NPATH / 16, 256>>>(lens);
    k_logits<<<NPATH / 8, 256>>>(ap, seg);
    k_expsum<<<NPATH / 256, 256>>>(seg);
    k_wsum<<<NPATH / 8, 256>>>(seg);
    k_head<<<GRP / 16, 256>>>(W_out, W_cls, ap, out, out_size);
}